// round 7
// baseline (speedup 1.0000x reference)
#include <cuda_runtime.h>
#include <cuda_bf16.h>
#include <math.h>
#include <stdint.h>
#include <stddef.h>

// Problem constants (fixed by the reference setup_inputs)
#define BATCH  2
#define NTOK   4096
#define DMODEL 512
#define HEADS  8
#define HDIM   64
#define KNN    9
#define MROWS  (BATCH * NTOK)          // 8192
#define GRID   64
#define CELLS  (GRID * GRID)
#define CELLSZ 1.5625f                 // 100/64
#define INVCELL 0.64f                  // 64/100

// Scratch (static __device__ arrays: allocation-free, harness-legal)
__device__ __nv_bfloat16  g_qkvb[(size_t)MROWS * 3 * DMODEL];    // bf16 Q|K|V
__device__ __nv_bfloat16  g_attnb[(size_t)MROWS * DMODEL];       // bf16 GELU(attn)
__device__ __nv_bfloat16  g_xb[(size_t)MROWS * DMODEL];          // bf16 x
__device__ __nv_bfloat16  g_wqb[(size_t)3 * DMODEL * DMODEL];    // bf16 w_qkv
__device__ __nv_bfloat16  g_wpb[(size_t)DMODEL * DMODEL];        // bf16 w_proj
__device__ int            g_nn[(size_t)MROWS * KNN];
__device__ int            g_cellstart[BATCH * (CELLS + 1)];
__device__ float2         g_scoord[BATCH * NTOK];
__device__ int            g_sidx[BATCH * NTOK];

// ===========================================================================
// PTX helpers (base sm_103 ISA: cp.async + ldmatrix + bf16 mma.sync)
// ===========================================================================
__device__ __forceinline__ void cp16(uint32_t saddr, const void* g) {
    asm volatile("cp.async.cg.shared.global [%0], [%1], 16;" :: "r"(saddr), "l"(g));
}
#define CP_COMMIT() asm volatile("cp.async.commit_group;" ::: "memory")
#define CP_WAIT1()  asm volatile("cp.async.wait_group 1;" ::: "memory")
#define CP_WAIT0()  asm volatile("cp.async.wait_group 0;" ::: "memory")

__device__ __forceinline__ void ldsm4(uint32_t* r, uint32_t addr) {
    asm volatile("ldmatrix.sync.aligned.m8n8.x4.shared.b16 {%0,%1,%2,%3}, [%4];"
                 : "=r"(r[0]), "=r"(r[1]), "=r"(r[2]), "=r"(r[3]) : "r"(addr));
}
__device__ __forceinline__ void mma_bf16(float* d, const uint32_t* a, const uint32_t* b) {
    asm volatile(
        "mma.sync.aligned.m16n8k16.row.col.f32.bf16.bf16.f32 "
        "{%0,%1,%2,%3},{%4,%5,%6,%7},{%8,%9},{%0,%1,%2,%3};"
        : "+f"(d[0]), "+f"(d[1]), "+f"(d[2]), "+f"(d[3])
        : "r"(a[0]), "r"(a[1]), "r"(a[2]), "r"(a[3]), "r"(b[0]), "r"(b[1]));
}

// ===========================================================================
// bf16 tensor-core NT GEMM body (fp32 accum).
// CTA 128x128, BK=64 (128B smem rows, 3-bit XOR swizzle), 3-stage cp.async
// ring, ONE barrier per 64-deep k-tile, warp grid 4x2 (32x64), ldmatrix.
// MODE 1: C fp32 += bias[n] + resid[m*N+n].   MODE 2: bf16 out -> g_qkvb.
// smem: 3 stages x (16KB A + 16KB B) = 96KB dynamic. Requires K%64==0.
// ===========================================================================
template <int MODE>
__device__ __forceinline__ void gemm_body_bf16(
    const __nv_bfloat16* __restrict__ A, const __nv_bfloat16* __restrict__ B,
    float* __restrict__ C, int N, int Kd,
    const float* __restrict__ bias, const float* __restrict__ resid,
    int bm, int bn, unsigned char* smem)
{
    const int tid  = threadIdx.x;
    const int warp = tid >> 5;
    const int lane = tid & 31;
    const int wm   = warp & 3;
    const int wn   = warp >> 2;
    const uint32_t sbase = (uint32_t)__cvta_generic_to_shared(smem);

    // cp.async fill: per stage, A = 128 rows x 8 chunks(16B) = 1024 chunks,
    // thread t covers chunkids {t, t+256, t+512, t+768}; same for B.
    const int frow = tid >> 3;          // base row 0..31 (+32,+64,+96)
    const int fc   = tid & 7;           // chunk 0..7
    uint32_t fdst[4];
    #pragma unroll
    for (int i = 0; i < 4; i++) {
        const int row = frow + 32 * i;
        fdst[i] = row * 128 + ((fc ^ (row & 7)) << 4);
    }
    const __nv_bfloat16* gA[4];
    const __nv_bfloat16* gB[4];
    #pragma unroll
    for (int i = 0; i < 4; i++) {
        gA[i] = A + (size_t)(bm + frow + 32 * i) * Kd + fc * 8;
        gB[i] = B + (size_t)(bn + frow + 32 * i) * Kd + fc * 8;
    }

    // ldmatrix lane addressing (rows of 128B, chunk_phys = chunk ^ (row&7))
    const int l7 = lane & 7;
    int rowA[2], swA[2];
    #pragma unroll
    for (int am = 0; am < 2; am++) {
        const int row = wm * 32 + am * 16 + ((lane >> 3) & 1) * 8 + l7;
        rowA[am] = row * 128;  swA[am] = row & 7;
    }
    const int cselA = lane >> 4;
    int rowB[4], swB[4];
    #pragma unroll
    for (int bp = 0; bp < 4; bp++) {
        const int row = wn * 64 + bp * 16 + ((lane >> 4) << 3) + l7;
        rowB[bp] = row * 128;  swB[bp] = row & 7;
    }
    const int cselB = (lane >> 3) & 1;

    float acc[2][8][4];
    #pragma unroll
    for (int i = 0; i < 2; i++)
        #pragma unroll
        for (int j = 0; j < 8; j++)
            #pragma unroll
            for (int q = 0; q < 4; q++) acc[i][j][q] = 0.f;

    const int T = Kd >> 6;   // BK = 64; T >= 2 for all our shapes

    #pragma unroll
    for (int s = 0; s < 2; ++s) {     // prologue: tiles 0,1 -> stages 0,1
        const int k0 = s << 6;
        const uint32_t sa = sbase + s * 32768, sb = sa + 16384;
        #pragma unroll
        for (int i = 0; i < 4; i++) { cp16(sa + fdst[i], gA[i] + k0); }
        #pragma unroll
        for (int i = 0; i < 4; i++) { cp16(sb + fdst[i], gB[i] + k0); }
        CP_COMMIT();
    }

    int stage = 0;
    for (int t = 0; t < T; ++t) {
        if (t + 1 < T) CP_WAIT1(); else CP_WAIT0();
        __syncthreads();

        if (t + 2 < T) {
            int s2 = stage + 2; if (s2 >= 3) s2 -= 3;
            const int k0 = (t + 2) << 6;
            const uint32_t sa = sbase + s2 * 32768, sb = sa + 16384;
            #pragma unroll
            for (int i = 0; i < 4; i++) { cp16(sa + fdst[i], gA[i] + k0); }
            #pragma unroll
            for (int i = 0; i < 4; i++) { cp16(sb + fdst[i], gB[i] + k0); }
            CP_COMMIT();
        }

        const uint32_t sa = sbase + stage * 32768, sb = sa + 16384;
        #pragma unroll
        for (int g = 0; g < 4; ++g) {     // four k16 steps per k-tile
            uint32_t af[2][4], bf[4][4];
            #pragma unroll
            for (int am = 0; am < 2; am++)
                ldsm4(af[am], sa + rowA[am] + ((((g << 1) | cselA) ^ swA[am]) << 4));
            #pragma unroll
            for (int bp = 0; bp < 4; bp++)
                ldsm4(bf[bp], sb + rowB[bp] + ((((g << 1) | cselB) ^ swB[bp]) << 4));
            #pragma unroll
            for (int am = 0; am < 2; am++)
                #pragma unroll
                for (int nb = 0; nb < 8; nb++)
                    mma_bf16(acc[am][nb], af[am], &bf[nb >> 1][(nb & 1) << 1]);
        }
        if (++stage == 3) stage = 0;
    }

    // ---- epilogue ----
    const int r4 = lane >> 2, c4 = lane & 3;
    #pragma unroll
    for (int am = 0; am < 2; ++am) {
        const int m0 = bm + wm * 32 + am * 16 + r4;
        #pragma unroll
        for (int nb = 0; nb < 8; ++nb) {
            const int n0 = bn + wn * 64 + nb * 8 + c4 * 2;
            float2 v01 = make_float2(acc[am][nb][0], acc[am][nb][1]);
            float2 v23 = make_float2(acc[am][nb][2], acc[am][nb][3]);
            if (MODE == 1) {
                const float2 bz = *(const float2*)(bias + n0);
                const float2 q0 = *(const float2*)(resid + (size_t)m0 * N + n0);
                const float2 q1 = *(const float2*)(resid + (size_t)(m0 + 8) * N + n0);
                v01.x += bz.x + q0.x;  v01.y += bz.y + q0.y;
                v23.x += bz.x + q1.x;  v23.y += bz.y + q1.y;
                *(float2*)(C + (size_t)m0 * N + n0)       = v01;
                *(float2*)(C + (size_t)(m0 + 8) * N + n0) = v23;
            } else {  // MODE 2: bf16 QKV
                *(__nv_bfloat162*)(g_qkvb + (size_t)m0 * N + n0)
                    = __floats2bfloat162_rn(v01.x, v01.y);
                *(__nv_bfloat162*)(g_qkvb + (size_t)(m0 + 8) * N + n0)
                    = __floats2bfloat162_rn(v23.x, v23.y);
            }
        }
    }
}

// ===========================================================================
// prep kernel: blocks 0..1 build the per-batch spatial grid; rest convert
// fp32 -> bf16 (x, w_qkv, w_proj).
// ===========================================================================
__global__ void __launch_bounds__(1024) prep_kernel(
    const float* __restrict__ x, const float* __restrict__ coords,
    const float* __restrict__ w_qkv, const float* __restrict__ w_proj)
{
    if (blockIdx.x < BATCH) {
        const int b = blockIdx.x;
        __shared__ int cnt[CELLS];
        __shared__ int part[1024];
        const int t = threadIdx.x;
        #pragma unroll
        for (int i = t; i < CELLS; i += 1024) cnt[i] = 0;
        __syncthreads();

        const float2* cb = (const float2*)coords + (size_t)b * NTOK;
        int pcid[4]; float2 pc[4];
        #pragma unroll
        for (int j = 0; j < 4; j++) {
            const int p = t + j * 1024;
            const float2 c = cb[p];
            const int cx = min(GRID - 1, max(0, (int)(c.x * INVCELL)));
            const int cy = min(GRID - 1, max(0, (int)(c.y * INVCELL)));
            pcid[j] = cy * GRID + cx;  pc[j] = c;
            atomicAdd(&cnt[pcid[j]], 1);
        }
        __syncthreads();

        const int c0 = cnt[t*4], c1 = cnt[t*4+1], c2 = cnt[t*4+2], c3 = cnt[t*4+3];
        const int lsum = c0 + c1 + c2 + c3;
        part[t] = lsum;
        __syncthreads();
        for (int off = 1; off < 1024; off <<= 1) {
            const int v = (t >= off) ? part[t - off] : 0;
            __syncthreads();
            part[t] += v;
            __syncthreads();
        }
        const int excl = part[t] - lsum;
        const int s0 = excl, s1 = excl + c0, s2 = s1 + c1, s3 = s2 + c2;
        cnt[t*4] = s0; cnt[t*4+1] = s1; cnt[t*4+2] = s2; cnt[t*4+3] = s3;
        int* csg = g_cellstart + b * (CELLS + 1);
        csg[t*4] = s0; csg[t*4+1] = s1; csg[t*4+2] = s2; csg[t*4+3] = s3;
        if (t == 1023) csg[CELLS] = NTOK;
        __syncthreads();

        #pragma unroll
        for (int j = 0; j < 4; j++) {
            const int pos = atomicAdd(&cnt[pcid[j]], 1);
            g_scoord[b * NTOK + pos] = pc[j];
            g_sidx[b * NTOK + pos]   = t + j * 1024;
        }
    } else {
        constexpr long XQ = (long)MROWS * DMODEL / 4;
        constexpr long WQ = (long)3 * DMODEL * DMODEL / 4;
        constexpr long WP = (long)DMODEL * DMODEL / 4;
        const long nb = gridDim.x - BATCH;
        for (long i = (long)(blockIdx.x - BATCH) * 1024 + threadIdx.x;
             i < XQ + WQ + WP; i += nb * 1024) {
            const float4* src; uint2* dst; long off;
            if (i < XQ)            { src = (const float4*)x;      dst = (uint2*)g_xb;  off = i; }
            else if (i < XQ + WQ)  { src = (const float4*)w_qkv;  dst = (uint2*)g_wqb; off = i - XQ; }
            else                   { src = (const float4*)w_proj; dst = (uint2*)g_wpb; off = i - XQ - WQ; }
            const float4 v = src[off];
            const __nv_bfloat162 lo = __floats2bfloat162_rn(v.x, v.y);
            const __nv_bfloat162 hi = __floats2bfloat162_rn(v.z, v.w);
            uint2 o; o.x = *(const uint32_t*)&lo; o.y = *(const uint32_t*)&hi;
            dst[off] = o;
        }
    }
}

// ===========================================================================
// grid kNN query: one thread per query; exact top-9 via ring expansion.
// ===========================================================================
__device__ __forceinline__ void scan_cell(
    int X, int Y, float qx, float qy,
    const int* __restrict__ cs, const float2* __restrict__ sc,
    const int* __restrict__ si,
    float (&d9)[KNN], int (&i9)[KNN], float& dmax, int& imax)
{
    const float lx = X * CELLSZ, ly = Y * CELLSZ;
    const float ddx = fmaxf(0.f, fmaxf(lx - qx, qx - (lx + CELLSZ)));
    const float ddy = fmaxf(0.f, fmaxf(ly - qy, qy - (ly + CELLSZ)));
    if (ddx * ddx + ddy * ddy >= dmax) return;
    const int cid = Y * GRID + X;
    const int s1 = cs[cid + 1];
    for (int s = cs[cid]; s < s1; ++s) {
        const float2 p = sc[s];
        const float dx = p.x - qx, dy = p.y - qy;
        const float d2 = dx * dx + dy * dy;
        if (d2 < dmax) {
            const int idx = si[s];
            #pragma unroll
            for (int j = 0; j < KNN; j++)
                if (j == imax) { d9[j] = d2; i9[j] = idx; }
            dmax = d9[0]; imax = 0;
            #pragma unroll
            for (int j = 1; j < KNN; j++)
                if (d9[j] > dmax) { dmax = d9[j]; imax = j; }
        }
    }
}

__device__ __forceinline__ void knn_query(const float* __restrict__ coords, int q)
{
    const int b = q >> 12, n = q & (NTOK - 1);
    const float2 qc = ((const float2*)coords)[(size_t)b * NTOK + n];
    const float qx = qc.x, qy = qc.y;
    const int cx = min(GRID - 1, max(0, (int)(qx * INVCELL)));
    const int cy = min(GRID - 1, max(0, (int)(qy * INVCELL)));
    const int*    cs = g_cellstart + b * (CELLS + 1);
    const float2* sc = g_scoord + b * NTOK;
    const int*    si = g_sidx + b * NTOK;

    float d9[KNN]; int i9[KNN];
    #pragma unroll
    for (int j = 0; j < KNN; j++) { d9[j] = 3.4e38f; i9[j] = 0; }
    float dmax = 3.4e38f; int imax = 0;

    for (int r = 0; r < GRID; ++r) {
        const int xlo = max(cx - r, 0), xhi = min(cx + r, GRID - 1);
        if (r == 0) {
            scan_cell(cx, cy, qx, qy, cs, sc, si, d9, i9, dmax, imax);
        } else {
            if (cy - r >= 0)
                for (int X = xlo; X <= xhi; X++)
                    scan_cell(X, cy - r, qx, qy, cs, sc, si, d9, i9, dmax, imax);
            if (cy + r <= GRID - 1)
                for (int X = xlo; X <= xhi; X++)
                    scan_cell(X, cy + r, qx, qy, cs, sc, si, d9, i9, dmax, imax);
            const int yl = max(cy - r + 1, 0), yh = min(cy + r - 1, GRID - 1);
            if (cx - r >= 0)
                for (int Y = yl; Y <= yh; Y++)
                    scan_cell(cx - r, Y, qx, qy, cs, sc, si, d9, i9, dmax, imax);
            if (cx + r <= GRID - 1)
                for (int Y = yl; Y <= yh; Y++)
                    scan_cell(cx + r, Y, qx, qy, cs, sc, si, d9, i9, dmax, imax);
        }
        const float rs = r * CELLSZ;
        if (rs * rs >= dmax) break;
    }
    #pragma unroll
    for (int j = 0; j < KNN; j++) g_nn[(size_t)q * KNN + j] = i9[j];
}

// ===========================================================================
// Fused launch: blocks [0,32) = kNN; blocks [32, 800) = QKV GEMM (MODE 2).
// ===========================================================================
#define KNN_BLOCKS 32

__global__ void __launch_bounds__(256, 2) qkv_knn_kernel(const float* __restrict__ coords)
{
    extern __shared__ __align__(128) unsigned char smem[];
    if (blockIdx.x < KNN_BLOCKS) {
        knn_query(coords, blockIdx.x * 256 + threadIdx.x);
    } else {
        const int idx = blockIdx.x - KNN_BLOCKS;
        gemm_body_bf16<2>(g_xb, g_wqb, nullptr, 3 * DMODEL, DMODEL, nullptr, nullptr,
                          (idx / 12) * 128, (idx % 12) * 128, smem);
    }
}

__global__ void __launch_bounds__(256, 2) proj_kernel(
    float* __restrict__ C, const float* __restrict__ bias, const float* __restrict__ resid)
{
    extern __shared__ __align__(128) unsigned char smem[];
    gemm_body_bf16<1>(g_attnb, g_wpb, C, DMODEL, DMODEL, bias, resid,
                      blockIdx.y * 128, blockIdx.x * 128, smem);
}

// ---------------------------------------------------------------------------
// Attention over 9 neighbors (all bf16 QKV), fused exact-erf GELU, bf16 out.
// One block per token, one warp per head, 2 head-elems per lane.
// ---------------------------------------------------------------------------
__global__ void __launch_bounds__(256) attn_kernel()
{
    const int r    = blockIdx.x;
    const int b    = r >> 12;
    const int h    = threadIdx.x >> 5;
    const int lane = threadIdx.x & 31;

    __shared__ int idx[KNN];
    if (threadIdx.x < KNN)
        idx[threadIdx.x] = (b << 12) + g_nn[(size_t)r * KNN + threadIdx.x];
    __syncthreads();

    const int hoff = h * HDIM + lane * 2;
    const float2 qv = __bfloat1622float2(
        *(const __nv_bfloat162*)(g_qkvb + (size_t)r * (3 * DMODEL) + hoff));

    float logit[KNN];
    #pragma unroll
    for (int j = 0; j < KNN; j++) {
        const float2 kv = __bfloat1622float2(*(const __nv_bfloat162*)
            (g_qkvb + (size_t)idx[j] * (3 * DMODEL) + DMODEL + hoff));
        float p = qv.x * kv.x + qv.y * kv.y;
        #pragma unroll
        for (int s = 16; s; s >>= 1) p += __shfl_xor_sync(0xffffffffu, p, s);
        logit[j] = p * 0.125f;
    }

    float mx = logit[0];
    #pragma unroll
    for (int j = 1; j < KNN; j++) mx = fmaxf(mx, logit[j]);
    float sum = 0.f;
    #pragma unroll
    for (int j = 0; j < KNN; j++) { logit[j] = __expf(logit[j] - mx); sum += logit[j]; }
    const float inv = 1.f / sum;

    float2 acc = make_float2(0.f, 0.f);
    #pragma unroll
    for (int j = 0; j < KNN; j++) {
        const float2 vv = __bfloat1622float2(*(const __nv_bfloat162*)
            (g_qkvb + (size_t)idx[j] * (3 * DMODEL) + 2 * DMODEL + hoff));
        const float w = logit[j] * inv;
        acc.x = fmaf(w, vv.x, acc.x);
        acc.y = fmaf(w, vv.y, acc.y);
    }

    acc.x = 0.5f * acc.x * (1.f + erff(acc.x * 0.70710678118654752f));
    acc.y = 0.5f * acc.y * (1.f + erff(acc.y * 0.70710678118654752f));

    *(__nv_bfloat162*)(g_attnb + (size_t)r * DMODEL + h * HDIM + lane * 2)
        = __floats2bfloat162_rn(acc.x, acc.y);
}

// ---------------------------------------------------------------------------
// kernel_launch: x, coords, w_qkv, w_proj, b_proj  ->  out (fp32, B*N*D)
// ---------------------------------------------------------------------------
extern "C" void kernel_launch(void* const* d_in, const int* in_sizes, int n_in,
                              void* d_out, int out_size)
{
    const float* x      = (const float*)d_in[0];
    const float* coords = (const float*)d_in[1];
    const float* w_qkv  = (const float*)d_in[2];
    const float* w_proj = (const float*)d_in[3];
    const float* b_proj = (const float*)d_in[4];
    float* out = (float*)d_out;

    constexpr int SMEM = 98304;   // 3-stage ring: 3 x 32KB
    cudaFuncSetAttribute(qkv_knn_kernel, cudaFuncAttributeMaxDynamicSharedMemorySize, SMEM);
    cudaFuncSetAttribute(proj_kernel,    cudaFuncAttributeMaxDynamicSharedMemorySize, SMEM);

    // 1) grid build (2 blocks) + fp32->bf16 conversion
    prep_kernel<<<BATCH + 640, 1024>>>(x, coords, w_qkv, w_proj);

    // 2) kNN query (32 blocks, first) + QKV GEMM (768 blocks)
    qkv_knn_kernel<<<KNN_BLOCKS + 768, 256, SMEM>>>(coords);

    // 3) neighbor attention + GELU (bf16 out)
    attn_kernel<<<MROWS, 256>>>();

    // 4) output projection + bias + residual
    {
        dim3 grid(DMODEL / 128, MROWS / 128);
        proj_kernel<<<grid, 256, SMEM>>>(out, b_proj, x);
    }
}